// round 3
// baseline (speedup 1.0000x reference)
#include <cuda_runtime.h>
#include <math.h>

#define BB 2
#define NN 2048
#define DIMM 1024
#define HH 16
#define DH 64
#define MTOT (BB*NN)          // 4096

// ---------------- scratch (no cudaMalloc allowed) ----------------
__device__ float g_qkv[(size_t)MTOT * 3 * 1024];          // 4096 x 3072
__device__ float g_Q[(size_t)BB * HH * NN * DH];          // [B,H,N,D]
__device__ float g_K[(size_t)BB * HH * NN * DH];
__device__ float g_V[(size_t)BB * HH * NN * DH];
__device__ float g_aO[(size_t)MTOT * 1024];               // [B*N, H*D]

// ---------------- generic fp32 SGEMM: C[M,N] = A[M,K] @ B[K,N] ----------------
// 128x128 tile, BK=8, 256 threads, 8x8 per-thread with split fragments.
__global__ __launch_bounds__(256, 2)
void sgemm_kernel(const float* __restrict__ A, const float* __restrict__ Bm,
                  float* __restrict__ C, int Mdim, int Ndim, int Kdim) {
    __shared__ float As[8][128];
    __shared__ float Bs[8][128];
    int tid = threadIdx.x;
    int ttx = tid & 15, tty = tid >> 4;
    int m0 = blockIdx.y * 128, n0 = blockIdx.x * 128;

    float acc[8][8];
#pragma unroll
    for (int i = 0; i < 8; i++)
#pragma unroll
        for (int j = 0; j < 8; j++) acc[i][j] = 0.f;

    int arow = tid >> 1;            // 0..127
    int acol = (tid & 1) * 4;       // 0 or 4
    int brow = tid >> 5;            // 0..7
    int bcol = (tid & 31) * 4;      // 0..124

    const float* Aptr = A + (size_t)(m0 + arow) * Kdim + acol;
    const float* Bptr = Bm + (size_t)brow * Ndim + n0 + bcol;

    for (int k0 = 0; k0 < Kdim; k0 += 8) {
        float4 a4 = *(const float4*)Aptr;
        float4 b4 = *(const float4*)Bptr;
        __syncthreads();
        As[acol + 0][arow] = a4.x;
        As[acol + 1][arow] = a4.y;
        As[acol + 2][arow] = a4.z;
        As[acol + 3][arow] = a4.w;
        *(float4*)&Bs[brow][bcol] = b4;
        __syncthreads();
        Aptr += 8;
        Bptr += (size_t)8 * Ndim;
#pragma unroll
        for (int k = 0; k < 8; k++) {
            float4 a0 = *(const float4*)&As[k][tty * 4];
            float4 a1 = *(const float4*)&As[k][tty * 4 + 64];
            float4 b0 = *(const float4*)&Bs[k][ttx * 4];
            float4 b1 = *(const float4*)&Bs[k][ttx * 4 + 64];
            float ar[8] = {a0.x, a0.y, a0.z, a0.w, a1.x, a1.y, a1.z, a1.w};
            float br[8] = {b0.x, b0.y, b0.z, b0.w, b1.x, b1.y, b1.z, b1.w};
#pragma unroll
            for (int i = 0; i < 8; i++)
#pragma unroll
                for (int j = 0; j < 8; j++) acc[i][j] += ar[i] * br[j];
        }
    }

#pragma unroll
    for (int i = 0; i < 8; i++) {
        int m = m0 + ((i < 4) ? (tty * 4 + i) : (64 + tty * 4 + (i - 4)));
        float4 c0 = make_float4(acc[i][0], acc[i][1], acc[i][2], acc[i][3]);
        float4 c1 = make_float4(acc[i][4], acc[i][5], acc[i][6], acc[i][7]);
        *(float4*)&C[(size_t)m * Ndim + n0 + ttx * 4] = c0;
        *(float4*)&C[(size_t)m * Ndim + n0 + ttx * 4 + 64] = c1;
    }
}

// ---------------- RoPE + transpose to [B,H,N,D] ----------------
// one thread per (b,n,h,i) with i in [0,32): handles dims i and i+32 for q,k,v
__global__ void rope_kernel(const float* __restrict__ qkv,
                            float* __restrict__ Q, float* __restrict__ K,
                            float* __restrict__ V) {
    int idx = blockIdx.x * blockDim.x + threadIdx.x;
    if (idx >= BB * NN * HH * 32) return;
    int i = idx & 31;
    int h = (idx >> 5) & 15;
    int n = (idx >> 9) & 2047;
    int b = idx >> 20;

    const float* row = qkv + (size_t)(b * NN + n) * 3072;
    int c0 = h * 64 + i;
    float q1 = row[c0],        q2 = row[c0 + 32];
    float k1 = row[1024 + c0], k2 = row[1024 + c0 + 32];
    float v1 = row[2048 + c0], v2 = row[2048 + c0 + 32];

    double inv = pow(10000.0, -(double)i / 32.0);
    double ang = (double)n * inv;
    float c = (float)cos(ang), s = (float)sin(ang);

    size_t o = ((size_t)(b * HH + h) * NN + n) * 64 + i;
    Q[o]      = q1 * c - q2 * s;
    Q[o + 32] = q2 * c + q1 * s;
    K[o]      = k1 * c - k2 * s;
    K[o + 32] = k2 * c + k1 * s;
    V[o]      = v1;
    V[o + 32] = v2;
}

// ---------------- fp32 flash attention, BM=BN=64, D=64 ----------------
#define SSTR 68   // padded row stride (floats): 68 % 32 == 4 -> conflict-free frags

__global__ __launch_bounds__(128)
void flash_kernel(const float* __restrict__ Q, const float* __restrict__ K,
                  const float* __restrict__ V, float* __restrict__ O) {
    extern __shared__ float sm[];
    float* Qs = sm;                   // [64][68]
    float* Ks = sm + 64 * SSTR;       // [64][68], reused as P after S compute
    float* Vs = sm + 2 * 64 * SSTR;   // [64][68]

    int bh = blockIdx.y;              // b*H + h
    int qt = blockIdx.x;              // query tile
    int tid = threadIdx.x;
    int tx = tid & 7;                 // 8 col groups
    int ty = tid >> 3;                // 16 row groups

    const float* Qg = Q + ((size_t)bh * NN + qt * 64) * 64;
    const float* Kg = K + (size_t)bh * NN * 64;
    const float* Vg = V + (size_t)bh * NN * 64;

    // load Q tile (64x64 floats, float4 per slot)
#pragma unroll
    for (int it = 0; it < 8; it++) {
        int i = tid + it * 128;       // 1024 float4 slots
        int r = i >> 4;
        int c = (i & 15) * 4;
        *(float4*)&Qs[r * SSTR + c] = *(const float4*)(Qg + r * 64 + c);
    }

    float o[4][8];
    float mreg[4], lreg[4];
#pragma unroll
    for (int r = 0; r < 4; r++) {
        mreg[r] = -INFINITY;
        lreg[r] = 0.f;
#pragma unroll
        for (int c = 0; c < 8; c++) o[r][c] = 0.f;
    }

    for (int kt = 0; kt < NN / 64; kt++) {
        __syncthreads();   // prev iter's P/V reads done (also orders Q tile on kt=0)
#pragma unroll
        for (int it = 0; it < 8; it++) {
            int i = tid + it * 128;
            int r = i >> 4;
            int c = (i & 15) * 4;
            *(float4*)&Ks[r * SSTR + c] = *(const float4*)(Kg + (kt * 64 + r) * 64 + c);
            *(float4*)&Vs[r * SSTR + c] = *(const float4*)(Vg + (kt * 64 + r) * 64 + c);
        }
        __syncthreads();

        // ---- S = Q @ K^T (rows r*16+ty, cols c*8+tx) ----
        float s[4][8];
#pragma unroll
        for (int r = 0; r < 4; r++)
#pragma unroll
            for (int c = 0; c < 8; c++) s[r][c] = 0.f;

#pragma unroll 4
        for (int d = 0; d < 64; d += 4) {
            float4 qf[4];
#pragma unroll
            for (int r = 0; r < 4; r++)
                qf[r] = *(const float4*)&Qs[(r * 16 + ty) * SSTR + d];
#pragma unroll
            for (int c = 0; c < 8; c++) {
                float4 kf = *(const float4*)&Ks[(c * 8 + tx) * SSTR + d];
#pragma unroll
                for (int r = 0; r < 4; r++)
                    s[r][c] += qf[r].x * kf.x + qf[r].y * kf.y +
                               qf[r].z * kf.z + qf[r].w * kf.w;
            }
        }

        // ---- online softmax (scale = 1/sqrt(64) = 0.125) ----
#pragma unroll
        for (int r = 0; r < 4; r++) {
            float rm = -INFINITY;
#pragma unroll
            for (int c = 0; c < 8; c++) {
                s[r][c] *= 0.125f;
                rm = fmaxf(rm, s[r][c]);
            }
#pragma unroll
            for (int off = 1; off < 8; off <<= 1)
                rm = fmaxf(rm, __shfl_xor_sync(0xffffffffu, rm, off));

            float nm = fmaxf(mreg[r], rm);
            float alpha = __expf(mreg[r] - nm);
            float rs = 0.f;
#pragma unroll
            for (int c = 0; c < 8; c++) {
                float p = __expf(s[r][c] - nm);
                s[r][c] = p;
                rs += p;
            }
#pragma unroll
            for (int off = 1; off < 8; off <<= 1)
                rs += __shfl_xor_sync(0xffffffffu, rs, off);

            lreg[r] = lreg[r] * alpha + rs;
            mreg[r] = nm;
#pragma unroll
            for (int c = 0; c < 8; c++) o[r][c] *= alpha;
        }

        __syncthreads();   // all lanes done reading Ks
        // write P into Ks buffer
#pragma unroll
        for (int r = 0; r < 4; r++)
#pragma unroll
            for (int c = 0; c < 8; c++)
                Ks[(r * 16 + ty) * SSTR + c * 8 + tx] = s[r][c];
        __syncthreads();

        // ---- O += P @ V (O cols c*8+tx) ----
#pragma unroll 8
        for (int kk = 0; kk < 64; kk++) {
            float pr[4];
#pragma unroll
            for (int r = 0; r < 4; r++)
                pr[r] = Ks[(r * 16 + ty) * SSTR + kk];
#pragma unroll
            for (int c = 0; c < 8; c++) {
                float vv = Vs[kk * SSTR + c * 8 + tx];
#pragma unroll
                for (int r = 0; r < 4; r++) o[r][c] += pr[r] * vv;
            }
        }
    }

    // ---- epilogue: normalize, write [B,N,H*D] ----
    int b = bh >> 4, h = bh & 15;
#pragma unroll
    for (int r = 0; r < 4; r++) {
        float invl = 1.f / lreg[r];
        int n = qt * 64 + r * 16 + ty;
        float* orow = O + ((size_t)(b * NN + n)) * 1024 + h * 64;
#pragma unroll
        for (int c = 0; c < 8; c++)
            orow[c * 8 + tx] = o[r][c] * invl;
    }
}

// ---------------- launch ----------------
extern "C" void kernel_launch(void* const* d_in, const int* in_sizes, int n_in,
                              void* d_out, int out_size) {
    const float* x     = (const float*)d_in[0];
    const float* w_qkv = (const float*)d_in[1];
    const float* w_out = (const float*)d_in[2];
    float* out = (float*)d_out;

    float *qkv, *Q, *K, *V, *aO;
    cudaGetSymbolAddress((void**)&qkv, g_qkv);
    cudaGetSymbolAddress((void**)&Q, g_Q);
    cudaGetSymbolAddress((void**)&K, g_K);
    cudaGetSymbolAddress((void**)&V, g_V);
    cudaGetSymbolAddress((void**)&aO, g_aO);

    // 1) qkv = x @ w_qkv   (4096 x 3072 x 1024)
    sgemm_kernel<<<dim3(3072 / 128, 4096 / 128), 256>>>(x, w_qkv, qkv, MTOT, 3072, 1024);

    // 2) RoPE + transpose
    int nth = BB * NN * HH * 32;
    rope_kernel<<<(nth + 255) / 256, 256>>>(qkv, Q, K, V);

    // 3) flash attention
    static const size_t FLASH_SMEM = 3 * 64 * SSTR * sizeof(float);  // 52224
    cudaFuncSetAttribute(flash_kernel, cudaFuncAttributeMaxDynamicSharedMemorySize,
                         (int)FLASH_SMEM);
    flash_kernel<<<dim3(NN / 64, BB * HH), 128, FLASH_SMEM>>>(Q, K, V, aO);

    // 4) out = aO @ w_out  (4096 x 1024 x 1024)
    sgemm_kernel<<<dim3(1024 / 128, 4096 / 128), 256>>>(aO, w_out, out, MTOT, 1024, 1024);
}

// round 4
// speedup vs baseline: 1.0017x; 1.0017x over previous
#include <cuda_runtime.h>
#include <math.h>

#define BB 2
#define NN 2048
#define DIMM 1024
#define HH 16
#define DH 64
#define MTOT (BB*NN)          // 4096

// ---------------- scratch (no cudaMalloc allowed) ----------------
__device__ float g_qkv[(size_t)MTOT * 3 * 1024];          // 4096 x 3072
__device__ float g_Q[(size_t)BB * HH * NN * DH];          // [B,H,N,D]
__device__ float g_K[(size_t)BB * HH * NN * DH];
__device__ float g_V[(size_t)BB * HH * NN * DH];
__device__ float g_aO[(size_t)MTOT * 1024];               // [B*N, H*D]

// ---------------- generic fp32 SGEMM: C[M,N] = A[M,K] @ B[K,N] ----------------
// 128x128 tile, BK=8, 256 threads, 8x8 per-thread with split fragments.
__global__ __launch_bounds__(256, 2)
void sgemm_kernel(const float* __restrict__ A, const float* __restrict__ Bm,
                  float* __restrict__ C, int Mdim, int Ndim, int Kdim) {
    __shared__ float As[8][128];
    __shared__ float Bs[8][128];
    int tid = threadIdx.x;
    int ttx = tid & 15, tty = tid >> 4;
    int m0 = blockIdx.y * 128, n0 = blockIdx.x * 128;

    float acc[8][8];
#pragma unroll
    for (int i = 0; i < 8; i++)
#pragma unroll
        for (int j = 0; j < 8; j++) acc[i][j] = 0.f;

    int arow = tid >> 1;            // 0..127
    int acol = (tid & 1) * 4;       // 0 or 4
    int brow = tid >> 5;            // 0..7
    int bcol = (tid & 31) * 4;      // 0..124

    const float* Aptr = A + (size_t)(m0 + arow) * Kdim + acol;
    const float* Bptr = Bm + (size_t)brow * Ndim + n0 + bcol;

    for (int k0 = 0; k0 < Kdim; k0 += 8) {
        float4 a4 = *(const float4*)Aptr;
        float4 b4 = *(const float4*)Bptr;
        __syncthreads();
        As[acol + 0][arow] = a4.x;
        As[acol + 1][arow] = a4.y;
        As[acol + 2][arow] = a4.z;
        As[acol + 3][arow] = a4.w;
        *(float4*)&Bs[brow][bcol] = b4;
        __syncthreads();
        Aptr += 8;
        Bptr += (size_t)8 * Ndim;
#pragma unroll
        for (int k = 0; k < 8; k++) {
            float4 a0 = *(const float4*)&As[k][tty * 4];
            float4 a1 = *(const float4*)&As[k][tty * 4 + 64];
            float4 b0 = *(const float4*)&Bs[k][ttx * 4];
            float4 b1 = *(const float4*)&Bs[k][ttx * 4 + 64];
            float ar[8] = {a0.x, a0.y, a0.z, a0.w, a1.x, a1.y, a1.z, a1.w};
            float br[8] = {b0.x, b0.y, b0.z, b0.w, b1.x, b1.y, b1.z, b1.w};
#pragma unroll
            for (int i = 0; i < 8; i++)
#pragma unroll
                for (int j = 0; j < 8; j++) acc[i][j] += ar[i] * br[j];
        }
    }

#pragma unroll
    for (int i = 0; i < 8; i++) {
        int m = m0 + ((i < 4) ? (tty * 4 + i) : (64 + tty * 4 + (i - 4)));
        float4 c0 = make_float4(acc[i][0], acc[i][1], acc[i][2], acc[i][3]);
        float4 c1 = make_float4(acc[i][4], acc[i][5], acc[i][6], acc[i][7]);
        *(float4*)&C[(size_t)m * Ndim + n0 + ttx * 4] = c0;
        *(float4*)&C[(size_t)m * Ndim + n0 + ttx * 4 + 64] = c1;
    }
}

// ---------------- RoPE + transpose to [B,H,N,D] ----------------
// one thread per (b,n,h,i) with i in [0,32): handles dims i and i+32 for q,k,v
__global__ void rope_kernel(const float* __restrict__ qkv,
                            float* __restrict__ Q, float* __restrict__ K,
                            float* __restrict__ V) {
    int idx = blockIdx.x * blockDim.x + threadIdx.x;
    if (idx >= BB * NN * HH * 32) return;
    int i = idx & 31;
    int h = (idx >> 5) & 15;
    int n = (idx >> 9) & 2047;
    int b = idx >> 20;

    const float* row = qkv + (size_t)(b * NN + n) * 3072;
    int c0 = h * 64 + i;
    float q1 = row[c0],        q2 = row[c0 + 32];
    float k1 = row[1024 + c0], k2 = row[1024 + c0 + 32];
    float v1 = row[2048 + c0], v2 = row[2048 + c0 + 32];

    double inv = pow(10000.0, -(double)i / 32.0);
    double ang = (double)n * inv;
    float c = (float)cos(ang), s = (float)sin(ang);

    size_t o = ((size_t)(b * HH + h) * NN + n) * 64 + i;
    Q[o]      = q1 * c - q2 * s;
    Q[o + 32] = q2 * c + q1 * s;
    K[o]      = k1 * c - k2 * s;
    K[o + 32] = k2 * c + k1 * s;
    V[o]      = v1;
    V[o + 32] = v2;
}

// ---------------- fp32 flash attention, BM=BN=64, D=64 ----------------
#define SSTR 68   // padded row stride (floats): 68 % 32 == 4 -> conflict-free frags

__global__ __launch_bounds__(128)
void flash_kernel(const float* __restrict__ Q, const float* __restrict__ K,
                  const float* __restrict__ V, float* __restrict__ O) {
    extern __shared__ float sm[];
    float* Qs = sm;                   // [64][68]
    float* Ks = sm + 64 * SSTR;       // [64][68], reused as P after S compute
    float* Vs = sm + 2 * 64 * SSTR;   // [64][68]

    int bh = blockIdx.y;              // b*H + h
    int qt = blockIdx.x;              // query tile
    int tid = threadIdx.x;
    int tx = tid & 7;                 // 8 col groups
    int ty = tid >> 3;                // 16 row groups

    const float* Qg = Q + ((size_t)bh * NN + qt * 64) * 64;
    const float* Kg = K + (size_t)bh * NN * 64;
    const float* Vg = V + (size_t)bh * NN * 64;

    // load Q tile (64x64 floats, float4 per slot)
#pragma unroll
    for (int it = 0; it < 8; it++) {
        int i = tid + it * 128;       // 1024 float4 slots
        int r = i >> 4;
        int c = (i & 15) * 4;
        *(float4*)&Qs[r * SSTR + c] = *(const float4*)(Qg + r * 64 + c);
    }

    float o[4][8];
    float mreg[4], lreg[4];
#pragma unroll
    for (int r = 0; r < 4; r++) {
        mreg[r] = -INFINITY;
        lreg[r] = 0.f;
#pragma unroll
        for (int c = 0; c < 8; c++) o[r][c] = 0.f;
    }

    for (int kt = 0; kt < NN / 64; kt++) {
        __syncthreads();   // prev iter's P/V reads done (also orders Q tile on kt=0)
#pragma unroll
        for (int it = 0; it < 8; it++) {
            int i = tid + it * 128;
            int r = i >> 4;
            int c = (i & 15) * 4;
            *(float4*)&Ks[r * SSTR + c] = *(const float4*)(Kg + (kt * 64 + r) * 64 + c);
            *(float4*)&Vs[r * SSTR + c] = *(const float4*)(Vg + (kt * 64 + r) * 64 + c);
        }
        __syncthreads();

        // ---- S = Q @ K^T (rows r*16+ty, cols c*8+tx) ----
        float s[4][8];
#pragma unroll
        for (int r = 0; r < 4; r++)
#pragma unroll
            for (int c = 0; c < 8; c++) s[r][c] = 0.f;

#pragma unroll 4
        for (int d = 0; d < 64; d += 4) {
            float4 qf[4];
#pragma unroll
            for (int r = 0; r < 4; r++)
                qf[r] = *(const float4*)&Qs[(r * 16 + ty) * SSTR + d];
#pragma unroll
            for (int c = 0; c < 8; c++) {
                float4 kf = *(const float4*)&Ks[(c * 8 + tx) * SSTR + d];
#pragma unroll
                for (int r = 0; r < 4; r++)
                    s[r][c] += qf[r].x * kf.x + qf[r].y * kf.y +
                               qf[r].z * kf.z + qf[r].w * kf.w;
            }
        }

        // ---- online softmax (scale = 1/sqrt(64) = 0.125) ----
#pragma unroll
        for (int r = 0; r < 4; r++) {
            float rm = -INFINITY;
#pragma unroll
            for (int c = 0; c < 8; c++) {
                s[r][c] *= 0.125f;
                rm = fmaxf(rm, s[r][c]);
            }
#pragma unroll
            for (int off = 1; off < 8; off <<= 1)
                rm = fmaxf(rm, __shfl_xor_sync(0xffffffffu, rm, off));

            float nm = fmaxf(mreg[r], rm);
            float alpha = __expf(mreg[r] - nm);
            float rs = 0.f;
#pragma unroll
            for (int c = 0; c < 8; c++) {
                float p = __expf(s[r][c] - nm);
                s[r][c] = p;
                rs += p;
            }
#pragma unroll
            for (int off = 1; off < 8; off <<= 1)
                rs += __shfl_xor_sync(0xffffffffu, rs, off);

            lreg[r] = lreg[r] * alpha + rs;
            mreg[r] = nm;
#pragma unroll
            for (int c = 0; c < 8; c++) o[r][c] *= alpha;
        }

        __syncthreads();   // all lanes done reading Ks
        // write P into Ks buffer
#pragma unroll
        for (int r = 0; r < 4; r++)
#pragma unroll
            for (int c = 0; c < 8; c++)
                Ks[(r * 16 + ty) * SSTR + c * 8 + tx] = s[r][c];
        __syncthreads();

        // ---- O += P @ V (O cols c*8+tx) ----
#pragma unroll 8
        for (int kk = 0; kk < 64; kk++) {
            float pr[4];
#pragma unroll
            for (int r = 0; r < 4; r++)
                pr[r] = Ks[(r * 16 + ty) * SSTR + kk];
#pragma unroll
            for (int c = 0; c < 8; c++) {
                float vv = Vs[kk * SSTR + c * 8 + tx];
#pragma unroll
                for (int r = 0; r < 4; r++) o[r][c] += pr[r] * vv;
            }
        }
    }

    // ---- epilogue: normalize, write [B,N,H*D] ----
    int b = bh >> 4, h = bh & 15;
#pragma unroll
    for (int r = 0; r < 4; r++) {
        float invl = 1.f / lreg[r];
        int n = qt * 64 + r * 16 + ty;
        float* orow = O + ((size_t)(b * NN + n)) * 1024 + h * 64;
#pragma unroll
        for (int c = 0; c < 8; c++)
            orow[c * 8 + tx] = o[r][c] * invl;
    }
}

// ---------------- launch ----------------
extern "C" void kernel_launch(void* const* d_in, const int* in_sizes, int n_in,
                              void* d_out, int out_size) {
    const float* x     = (const float*)d_in[0];
    const float* w_qkv = (const float*)d_in[1];
    const float* w_out = (const float*)d_in[2];
    float* out = (float*)d_out;

    float *qkv, *Q, *K, *V, *aO;
    cudaGetSymbolAddress((void**)&qkv, g_qkv);
    cudaGetSymbolAddress((void**)&Q, g_Q);
    cudaGetSymbolAddress((void**)&K, g_K);
    cudaGetSymbolAddress((void**)&V, g_V);
    cudaGetSymbolAddress((void**)&aO, g_aO);

    // 1) qkv = x @ w_qkv   (4096 x 3072 x 1024)
    sgemm_kernel<<<dim3(3072 / 128, 4096 / 128), 256>>>(x, w_qkv, qkv, MTOT, 3072, 1024);

    // 2) RoPE + transpose
    int nth = BB * NN * HH * 32;
    rope_kernel<<<(nth + 255) / 256, 256>>>(qkv, Q, K, V);

    // 3) flash attention
    static const size_t FLASH_SMEM = 3 * 64 * SSTR * sizeof(float);  // 52224
    cudaFuncSetAttribute(flash_kernel, cudaFuncAttributeMaxDynamicSharedMemorySize,
                         (int)FLASH_SMEM);
    flash_kernel<<<dim3(NN / 64, BB * HH), 128, FLASH_SMEM>>>(Q, K, V, aO);

    // 4) out = aO @ w_out  (4096 x 1024 x 1024)
    sgemm_kernel<<<dim3(1024 / 128, 4096 / 128), 256>>>(aO, w_out, out, MTOT, 1024, 1024);
}